// round 9
// baseline (speedup 1.0000x reference)
#include <cuda_runtime.h>

#define XNS 32
#define XNC 16
#define XT  64
#define XNB 512
#define XSC 48
#define QS  52   // padded row stride for 48-wide matrices (conflict-free float4 rows)
#define KS  36   // padded row stride for Kt

// gain scratch: per (b,t) 528 floats = [K 16x32][k 16]
__device__ float g_G[(size_t)XNB * XT * 528];
__device__ float g_cost[(size_t)XNB * XT];

__device__ __forceinline__ void cpa16(void* s, const void* g) {
    unsigned sa = (unsigned)__cvta_generic_to_shared(s);
    asm volatile("cp.async.cg.shared.global [%0], [%1], 16;" :: "r"(sa), "l"(g));
}
__device__ __forceinline__ void cpa_commit() { asm volatile("cp.async.commit_group;"); }
__device__ __forceinline__ void cpa_wait0()  { asm volatile("cp.async.wait_group 0;"); }

__global__ __launch_bounds__(256, 4)
void lqr_kernel(const float* __restrict__ Xi, const float* __restrict__ Qg,
                const float* __restrict__ Pg, const float* __restrict__ Ag,
                const float* __restrict__ Bg, float* __restrict__ out)
{
    __shared__ __align__(16) float sF[32 * QS];
    __shared__ __align__(16) float sM[32 * QS];     // backward: V@F ; forward: K dbl-buf
    __shared__ __align__(16) float sQt[48 * QS];    // Qt; its xx block doubles as V
    __shared__ __align__(16) float sQraw[48 * QS];
    __shared__ __align__(16) float scx[64 * 32];
    __shared__ __align__(16) float sKt[16 * KS];
    __shared__ __align__(16) float sqt[48];
    __shared__ float sv[32];
    __shared__ __align__(16) float sInv[16 * 20];
    __shared__ __align__(16) float sp[48];

    const int b   = blockIdx.x;
    const int tid = threadIdx.x;
    // rotate roles by whole warps so co-resident CTAs put their single-warp
    // phases (inversion, rollout) on different SMSPs. (lane id unchanged.)
    const int ltid = (tid + 256 - ((b % 7) << 5)) & 255;
    const int lane = tid & 31;
    const float* Qb = Qg + (size_t)b * XT * XSC * XSC;
    const float* Pb = Pg + (size_t)b * XT * XSC;

    // ---- setup ----
    for (int e = tid; e < 32 * 48; e += 256) {
        int s = e / 48, j = e % 48;
        sF[s * QS + j] = (j < 32) ? Ag[s * 32 + j] : Bg[s * 16 + (j - 32)];
    }
    // V := 0 lives in sQt[0:32, 0:32]
    for (int e = tid; e < 1024; e += 256) {
        int i = e >> 5, j = e & 31;
        sQt[i * QS + j] = 0.f;
    }
    if (tid < 32) sv[tid] = 0.f;
    {   // prefetch Q(T-1), p(T-1) into padded sQraw
        const float* qsrc = Qb + (size_t)(XT - 1) * XSC * XSC;
        #pragma unroll
        for (int kk = 0; kk < 3; kk++) {
            int idx = tid + kk * 256;
            if (idx < 576) {
                int row = idx / 12, off = idx % 12;
                cpa16(sQraw + row * QS + off * 4, qsrc + idx * 4);
            }
        }
        if (tid < 12) cpa16(sp + tid * 4, Pb + (size_t)(XT - 1) * XSC + tid * 4);
        cpa_commit();
    }
    __syncthreads();

    // nominal trajectory cx[t] (one rotated warp)
    if (ltid < 32) {
        scx[lane] = Xi[b * 32 + lane];
        for (int t = 1; t < XT; t++) {
            __syncwarp();
            float acc = 0.f;
            #pragma unroll
            for (int jj = 0; jj < 32; jj++) {
                int j = (lane + jj) & 31;
                acc += sF[lane * QS + j] * scx[(t - 1) * 32 + j];
            }
            scx[t * 32 + lane] = acc;
        }
    }
    __syncthreads();

    // =============== backward Riccati ===============
    for (int t = XT - 1; t >= 0; t--) {
        // A: M = V @ F (V symmetric, lives in sQt xx-block) 4x2 tiles, 192 thr
        if (ltid < 192) {
            const int s0 = (ltid / 24) * 4, j0 = (ltid % 24) * 2;
            float a00=0,a01=0,a10=0,a11=0,a20=0,a21=0,a30=0,a31=0;
            #pragma unroll 8
            for (int r = 0; r < 32; r++) {
                const float4 vv = *(const float4*)(sQt + r * QS + s0);
                const float2 ff = *(const float2*)(sF + r * QS + j0);
                a00 += vv.x*ff.x; a01 += vv.x*ff.y; a10 += vv.y*ff.x; a11 += vv.y*ff.y;
                a20 += vv.z*ff.x; a21 += vv.z*ff.y; a30 += vv.w*ff.x; a31 += vv.w*ff.y;
            }
            *(float2*)(sM + (s0+0)*QS + j0) = make_float2(a00,a01);
            *(float2*)(sM + (s0+1)*QS + j0) = make_float2(a10,a11);
            *(float2*)(sM + (s0+2)*QS + j0) = make_float2(a20,a21);
            *(float2*)(sM + (s0+3)*QS + j0) = make_float2(a30,a31);
        }
        cpa_wait0();
        __syncthreads();                           // Qraw(t), p(t), M ready

        // B: Qt = Qraw + F^T M (full, 144 thr, 4x4 float4 tiles)  ||  qt (48 thr)
        if (ltid < 144) {
            const int i0 = (ltid / 12) * 4, j0 = (ltid % 12) * 4;
            float4 c0 = *(const float4*)(sQraw + (i0+0)*QS + j0);
            float4 c1 = *(const float4*)(sQraw + (i0+1)*QS + j0);
            float4 c2 = *(const float4*)(sQraw + (i0+2)*QS + j0);
            float4 c3 = *(const float4*)(sQraw + (i0+3)*QS + j0);
            #pragma unroll 4
            for (int s = 0; s < 32; s++) {
                const float4 fa = *(const float4*)(sF + s * QS + i0);
                const float4 mb = *(const float4*)(sM + s * QS + j0);
                c0.x += fa.x*mb.x; c0.y += fa.x*mb.y; c0.z += fa.x*mb.z; c0.w += fa.x*mb.w;
                c1.x += fa.y*mb.x; c1.y += fa.y*mb.y; c1.z += fa.y*mb.z; c1.w += fa.y*mb.w;
                c2.x += fa.z*mb.x; c2.y += fa.z*mb.y; c2.z += fa.z*mb.z; c2.w += fa.z*mb.w;
                c3.x += fa.w*mb.x; c3.y += fa.w*mb.y; c3.z += fa.w*mb.z; c3.w += fa.w*mb.w;
            }
            *(float4*)(sQt + (i0+0)*QS + j0) = c0;
            *(float4*)(sQt + (i0+1)*QS + j0) = c1;
            *(float4*)(sQt + (i0+2)*QS + j0) = c2;
            *(float4*)(sQt + (i0+3)*QS + j0) = c3;
        } else if (ltid >= 208) {
            const int i = ltid - 208;
            float acc = sp[i];
            #pragma unroll
            for (int jj = 0; jj < 32; jj++) {
                int j = (i + jj) & 31;
                acc += sQraw[i * QS + j] * scx[t * 32 + j];
            }
            #pragma unroll
            for (int s = 0; s < 32; s++) acc += sv[s] * sF[s * QS + i];
            sqt[i] = acc;
        }
        __syncthreads();                           // Qt, qt ready; Qraw free

        // C: prefetch next Q,p  +  rotated-warp GJ inverse of Quu
        if (t > 0) {
            const float* qsrc = Qb + (size_t)(t - 1) * XSC * XSC;
            #pragma unroll
            for (int kk = 0; kk < 3; kk++) {
                int idx = tid + kk * 256;
                if (idx < 576) {
                    int row = idx / 12, off = idx % 12;
                    cpa16(sQraw + row * QS + off * 4, qsrc + idx * 4);
                }
            }
            if (tid < 12) cpa16(sp + tid * 4, Pb + (size_t)(t - 1) * XSC + tid * 4);
            cpa_commit();
        }
        if (ltid < 32) {
            const int col = lane & 15;
            float creg[16];
            if (lane < 16) {
                #pragma unroll
                for (int i2 = 0; i2 < 16; i2++) creg[i2] = sQt[(32+i2)*QS + 32 + lane];
            } else {
                #pragma unroll
                for (int i2 = 0; i2 < 16; i2++) creg[i2] = (i2 == col) ? 1.f : 0.f;
            }
            #pragma unroll
            for (int k = 0; k < 16; k++) {
                const float ck  = __shfl_sync(0xffffffffu, creg[k], k);
                const float piv = 1.0f / ck;
                creg[k] *= piv;
                #pragma unroll
                for (int i2 = 0; i2 < 16; i2++) {
                    if (i2 == k) continue;
                    const float cik = __shfl_sync(0xffffffffu, creg[i2], k);
                    creg[i2] -= cik * creg[k];
                }
            }
            if (lane >= 16) {
                #pragma unroll
                for (int i2 = 0; i2 < 16; i2++) sInv[i2 * 20 + col] = creg[i2];
            }
        }
        __syncthreads();                           // Inv ready

        // DE fused: all 8 warps. Warp w owns columns j0 = 4w.
        //   step1: Kt[:, j0:j0+4] = -Inv @ Qux[:, j0:j0+4]   (+ warp0: kt)
        //   step2: Vn[:, j0:j0+4] = Qxx + Qxu Kt[:, j0:j0+4] in place (+ warp0: vn)
        {
            const int w  = ltid >> 5;
            const int j0 = w * 4;
            const int a  = lane & 15;
            const int jp = lane >> 4;
            float* gdst = g_G + ((size_t)b * XT + t) * 528;

            float invr[16];
            *(float4*)&invr[0]  = *(const float4*)(sInv + a*20 + 0);
            *(float4*)&invr[4]  = *(const float4*)(sInv + a*20 + 4);
            *(float4*)&invr[8]  = *(const float4*)(sInv + a*20 + 8);
            *(float4*)&invr[12] = *(const float4*)(sInv + a*20 + 12);

            float acc0 = 0.f, acc1 = 0.f;
            #pragma unroll
            for (int c = 0; c < 16; c++) {
                const float2 q = *(const float2*)(sQt + (32+c)*QS + j0 + 2*jp);
                acc0 += invr[c] * q.x;
                acc1 += invr[c] * q.y;
            }
            acc0 = -acc0; acc1 = -acc1;
            *(float2*)(sKt + a*KS + j0 + 2*jp) = make_float2(acc0, acc1);
            *(float2*)(gdst + a*32 + j0 + 2*jp) = make_float2(acc0, acc1);

            float ktv = 0.f;
            if (w == 0 && lane < 16) {             // kt on warp 0 lanes 0-15
                float qu[16];
                *(float4*)&qu[0]  = *(const float4*)(sqt + 32);
                *(float4*)&qu[4]  = *(const float4*)(sqt + 36);
                *(float4*)&qu[8]  = *(const float4*)(sqt + 40);
                *(float4*)&qu[12] = *(const float4*)(sqt + 44);
                #pragma unroll
                for (int c = 0; c < 16; c++) ktv += invr[c] * qu[c];
                ktv = -ktv;
                gdst[512 + a] = ktv;
            }
            __syncwarp();

            // step2
            const int i = lane;
            float4 vacc = *(const float4*)(sQt + i*QS + j0);
            float qxu[16];
            *(float4*)&qxu[0]  = *(const float4*)(sQt + i*QS + 32);
            *(float4*)&qxu[4]  = *(const float4*)(sQt + i*QS + 36);
            *(float4*)&qxu[8]  = *(const float4*)(sQt + i*QS + 40);
            *(float4*)&qxu[12] = *(const float4*)(sQt + i*QS + 44);
            #pragma unroll
            for (int a2 = 0; a2 < 16; a2++) {
                const float4 kr = *(const float4*)(sKt + a2*KS + j0);
                vacc.x += qxu[a2] * kr.x;
                vacc.y += qxu[a2] * kr.y;
                vacc.z += qxu[a2] * kr.z;
                vacc.w += qxu[a2] * kr.w;
            }
            *(float4*)(sQt + i*QS + j0) = vacc;    // V for next step, in place

            if (w == 0) {                          // vn on warp 0 (shfl kt)
                float vn = sqt[i];
                #pragma unroll
                for (int a2 = 0; a2 < 16; a2++)
                    vn += qxu[a2] * __shfl_sync(0xffffffffu, ktv, a2);
                sv[i] = vn;
            }
        }
        __syncthreads();                           // V, v ready for next step
    }

    // =============== forward rollout: one rotated warp, shuffle-resident state ==
    if (ltid < 32) {
        float* kb0 = sM;
        float* kb1 = sM + 544;
        float* out_x = out;
        float* out_u = out + (size_t)XNB * XT * XNS;
        float x = Xi[b * 32 + lane];
        {
            const float* src = g_G + (size_t)b * XT * 528;
            #pragma unroll
            for (int kk = 0; kk < 5; kk++) {
                int e = lane + kk * 32;
                if (e < 132) cpa16(kb0 + e * 4, src + e * 4);
            }
            cpa_commit();
        }
        int pb = 0;
        for (int t = 0; t < XT; t++) {
            cpa_wait0();
            __syncwarp();
            const float* kc = pb ? kb1 : kb0;
            const float d = x - scx[t * 32 + lane];
            float acc = 0.f;
            #pragma unroll
            for (int jj = 0; jj < 32; jj++) {
                int j = (lane + jj) & 31;
                float dj = __shfl_sync(0xffffffffu, d, j);
                if (lane < 16) acc += kc[lane * 32 + j] * dj;
            }
            float u = 0.f;
            if (lane < 16) {
                u = acc + kc[512 + lane];
                out_u[((size_t)b * XT + t) * XNC + lane] = u;
            }
            out_x[((size_t)b * XT + t) * XNS + lane] = x;
            if (t + 1 < XT) {
                const float* src = g_G + ((size_t)b * XT + t + 1) * 528;
                float* kn = pb ? kb0 : kb1;
                #pragma unroll
                for (int kk = 0; kk < 5; kk++) {
                    int e = lane + kk * 32;
                    if (e < 132) cpa16(kn + e * 4, src + e * 4);
                }
                cpa_commit();
            }
            float xn = 0.f, xn2 = 0.f;
            #pragma unroll
            for (int jj = 0; jj < 32; jj++) {
                int j = (lane + jj) & 31;
                float xj = __shfl_sync(0xffffffffu, x, j);
                if (jj & 1) xn2 += sF[lane * QS + j] * xj;
                else        xn  += sF[lane * QS + j] * xj;
            }
            #pragma unroll
            for (int aa = 0; aa < 16; aa++) {
                int a2 = (lane + aa) & 15;
                float ua = __shfl_sync(0xffffffffu, u, a2);
                if (aa & 1) xn2 += sF[lane * QS + 32 + a2] * ua;
                else        xn  += sF[lane * QS + 32 + a2] * ua;
            }
            x = xn + xn2;
            pb ^= 1;
        }
    }
}

// ---- cost: parallel over (b,t), deterministic per-tile reduction ----
__global__ __launch_bounds__(128)
void cost_kernel(const float* __restrict__ Qg, const float* __restrict__ Pg,
                 const float* __restrict__ outbuf)
{
    const int t = blockIdx.x, b = blockIdx.y, tid = threadIdx.x;
    __shared__ float sxu[48];
    __shared__ float red[4];
    const float* out_x = outbuf;
    const float* out_u = outbuf + (size_t)XNB * XT * XNS;
    if (tid < 32) sxu[tid] = out_x[((size_t)b * XT + t) * XNS + tid];
    else if (tid < 48) sxu[tid] = out_u[((size_t)b * XT + t) * XNC + (tid - 32)];
    __syncthreads();

    const float4* Qt = (const float4*)(Qg + ((size_t)b * XT + t) * XSC * XSC);
    float part = 0.f;
    #pragma unroll
    for (int kk = 0; kk < 5; kk++) {
        int idx = tid + kk * 128;
        if (idx < 576) {
            float4 qv = Qt[idx];
            int base = idx * 4;
            int i = base / 48, j = base % 48;
            part += sxu[i] * (qv.x * sxu[j] + qv.y * sxu[j+1] + qv.z * sxu[j+2] + qv.w * sxu[j+3]);
        }
    }
    part *= 0.5f;
    if (tid < 48) part += sxu[tid] * Pg[((size_t)b * XT + t) * XSC + tid];

    #pragma unroll
    for (int off = 16; off > 0; off >>= 1)
        part += __shfl_down_sync(0xffffffffu, part, off);
    if ((tid & 31) == 0) red[tid >> 5] = part;
    __syncthreads();
    if (tid == 0) g_cost[(size_t)b * XT + t] = (red[0] + red[1]) + (red[2] + red[3]);
}

__global__ void cost_reduce(float* __restrict__ outbuf)
{
    const int b = blockIdx.x * 256 + threadIdx.x;
    if (b < XNB) {
        float acc = 0.f;
        #pragma unroll 8
        for (int t = 0; t < XT; t++) acc += g_cost[(size_t)b * XT + t];
        outbuf[(size_t)XNB * XT * XNS + (size_t)XNB * XT * XNC + b] = acc;
    }
}

extern "C" void kernel_launch(void* const* d_in, const int* in_sizes, int n_in,
                              void* d_out, int out_size) {
    const float* x_init = (const float*)d_in[0];
    const float* Q      = (const float*)d_in[1];
    const float* p      = (const float*)d_in[2];
    const float* A      = (const float*)d_in[3];
    const float* B      = (const float*)d_in[4];
    float* out = (float*)d_out;
    lqr_kernel<<<XNB, 256>>>(x_init, Q, p, A, B, out);
    cost_kernel<<<dim3(XT, XNB), 128>>>(Q, p, out);
    cost_reduce<<<2, 256>>>(out);
}

// round 10
// speedup vs baseline: 1.2336x; 1.2336x over previous
#include <cuda_runtime.h>

#define XNS 32
#define XNC 16
#define XT  64
#define XNB 512
#define XSC 48

// gain scratch: per (b,t) 528 floats = [K 16x32][k 16]
__device__ float g_G[(size_t)XNB * XT * 528];

__device__ __forceinline__ void cpa16(void* s, const void* g) {
    unsigned sa = (unsigned)__cvta_generic_to_shared(s);
    asm volatile("cp.async.cg.shared.global [%0], [%1], 16;" :: "r"(sa), "l"(g));
}
__device__ __forceinline__ void cpa_commit() { asm volatile("cp.async.commit_group;"); }
__device__ __forceinline__ void cpa_wait0()  { asm volatile("cp.async.wait_group 0;"); }

__global__ __launch_bounds__(256, 4)
void lqr_kernel(const float* __restrict__ Xi, const float* __restrict__ Qg,
                const float* __restrict__ Pg, const float* __restrict__ Ag,
                const float* __restrict__ Bg, float* __restrict__ out)
{
    __shared__ __align__(16) float sF[32 * 48];
    __shared__ __align__(16) float sV[32 * 36];     // padded rows
    __shared__ __align__(16) float sM[32 * 48];     // backward: V@F ; forward: K dbl-buf
    __shared__ __align__(16) float sQt[48 * 48];
    __shared__ __align__(16) float sQraw[48 * 48];
    __shared__ __align__(16) float scx[64 * 32];
    __shared__ __align__(16) float sKt[16 * 32];
    __shared__ __align__(16) float skt[16];
    __shared__ __align__(16) float sqt[48];
    __shared__ float sv[32];
    __shared__ __align__(16) float sInv[16 * 20];   // stride 20: float4-loadable rows
    __shared__ __align__(16) float sp[48];
    __shared__ float scc[48];                       // cost accumulators

    const int b   = blockIdx.x;
    const int tid = threadIdx.x;
    const float* Qb = Qg + (size_t)b * XT * XSC * XSC;
    const float* Pb = Pg + (size_t)b * XT * XSC;

    // ---- setup ----
    for (int e = tid; e < 32 * 48; e += 256) {
        int s = e / 48, j = e % 48;
        sF[e] = (j < 32) ? Ag[s * 32 + j] : Bg[s * 16 + (j - 32)];
    }
    for (int e = tid; e < 32 * 36; e += 256) sV[e] = 0.f;
    if (tid < 32) sv[tid] = 0.f;
    if (tid < 48) scc[tid] = 0.f;
    {   // prefetch Q(T-1), p(T-1)
        const float* qsrc = Qb + (size_t)(XT - 1) * XSC * XSC;
        #pragma unroll
        for (int kk = 0; kk < 3; kk++) { int idx = tid + kk * 256;
            if (idx < 576) cpa16(sQraw + idx * 4, qsrc + idx * 4); }
        if (tid < 12) cpa16(sp + tid * 4, Pb + (size_t)(XT - 1) * XSC + tid * 4);
        cpa_commit();
    }
    __syncthreads();

    // nominal trajectory cx[t] (warp 0)
    if (tid < 32) {
        scx[tid] = Xi[b * 32 + tid];
        for (int t = 1; t < XT; t++) {
            __syncwarp();
            float acc = 0.f;
            #pragma unroll
            for (int jj = 0; jj < 32; jj++) {
                int j = (tid + jj) & 31;
                acc += sF[tid * 48 + j] * scx[(t - 1) * 32 + j];
            }
            scx[t * 32 + tid] = acc;
        }
    }
    __syncthreads();

    // =============== backward Riccati ===============
    for (int t = XT - 1; t >= 0; t--) {
        // A: M = V @ F (V symmetric: row reads)
        if (tid < 192) {
            const int s0 = (tid / 24) * 4, j0 = (tid % 24) * 2;
            float a00=0,a01=0,a10=0,a11=0,a20=0,a21=0,a30=0,a31=0;
            #pragma unroll 8
            for (int r = 0; r < 32; r++) {
                const float4 vv = *(const float4*)(sV + r * 36 + s0);
                const float2 ff = *(const float2*)(sF + r * 48 + j0);
                a00 += vv.x*ff.x; a01 += vv.x*ff.y; a10 += vv.y*ff.x; a11 += vv.y*ff.y;
                a20 += vv.z*ff.x; a21 += vv.z*ff.y; a30 += vv.w*ff.x; a31 += vv.w*ff.y;
            }
            *(float2*)(sM + (s0+0)*48 + j0) = make_float2(a00,a01);
            *(float2*)(sM + (s0+1)*48 + j0) = make_float2(a10,a11);
            *(float2*)(sM + (s0+2)*48 + j0) = make_float2(a20,a21);
            *(float2*)(sM + (s0+3)*48 + j0) = make_float2(a30,a31);
        }
        cpa_wait0();
        __syncthreads();                           // Qraw(t), p(t), M ready

        // B: Qt = Qraw + F^T M  ||  qt (+ stage-constant cost accumulation)
        if (tid < 144) {
            const int i0 = (tid / 12) * 4, j0 = (tid % 12) * 4;
            float4 c0 = *(const float4*)(sQraw + (i0+0)*48 + j0);
            float4 c1 = *(const float4*)(sQraw + (i0+1)*48 + j0);
            float4 c2 = *(const float4*)(sQraw + (i0+2)*48 + j0);
            float4 c3 = *(const float4*)(sQraw + (i0+3)*48 + j0);
            #pragma unroll 4
            for (int s = 0; s < 32; s++) {
                const float4 fa = *(const float4*)(sF + s * 48 + i0);
                const float4 mb = *(const float4*)(sM + s * 48 + j0);
                c0.x += fa.x*mb.x; c0.y += fa.x*mb.y; c0.z += fa.x*mb.z; c0.w += fa.x*mb.w;
                c1.x += fa.y*mb.x; c1.y += fa.y*mb.y; c1.z += fa.y*mb.z; c1.w += fa.y*mb.w;
                c2.x += fa.z*mb.x; c2.y += fa.z*mb.y; c2.z += fa.z*mb.z; c2.w += fa.z*mb.w;
                c3.x += fa.w*mb.x; c3.y += fa.w*mb.y; c3.z += fa.w*mb.z; c3.w += fa.w*mb.w;
            }
            *(float4*)(sQt + (i0+0)*48 + j0) = c0;
            *(float4*)(sQt + (i0+1)*48 + j0) = c1;
            *(float4*)(sQt + (i0+2)*48 + j0) = c2;
            *(float4*)(sQt + (i0+3)*48 + j0) = c3;
        } else if (tid >= 208) {
            const int i = tid - 208;
            float tmp = 0.f;                       // (Qraw_x* · cx)_i
            #pragma unroll
            for (int jj = 0; jj < 32; jj++) {
                int j = (i + jj) & 31;
                tmp += sQraw[i * 48 + j] * scx[t * 32 + j];
            }
            float acc = sp[i] + tmp;
            #pragma unroll
            for (int s = 0; s < 32; s++) acc += sv[s] * sF[s * 48 + i];
            sqt[i] = acc;
            if (i < 32)                            // stage const: cx_i (0.5 tmp + p_i)
                scc[i] += scx[t * 32 + i] * (0.5f * tmp + sp[i]);
        }
        __syncthreads();                           // Qt, qt ready; Qraw free

        // C: prefetch next Q,p  +  warp-0 GJ inverse of Quu
        if (t > 0) {
            const float* qsrc = Qb + (size_t)(t - 1) * XSC * XSC;
            #pragma unroll
            for (int kk = 0; kk < 3; kk++) { int idx = tid + kk * 256;
                if (idx < 576) cpa16(sQraw + idx * 4, qsrc + idx * 4); }
            if (tid < 12) cpa16(sp + tid * 4, Pb + (size_t)(t - 1) * XSC + tid * 4);
            cpa_commit();
        }
        if (tid < 32) {
            const int lane = tid, col = lane & 15;
            float creg[16];
            if (lane < 16) {
                #pragma unroll
                for (int i2 = 0; i2 < 16; i2++) creg[i2] = sQt[(32+i2)*48 + 32 + lane];
            } else {
                #pragma unroll
                for (int i2 = 0; i2 < 16; i2++) creg[i2] = (i2 == col) ? 1.f : 0.f;
            }
            #pragma unroll
            for (int k = 0; k < 16; k++) {
                const float ck  = __shfl_sync(0xffffffffu, creg[k], k);
                const float piv = 1.0f / ck;
                creg[k] *= piv;
                #pragma unroll
                for (int i2 = 0; i2 < 16; i2++) {
                    if (i2 == k) continue;
                    const float cik = __shfl_sync(0xffffffffu, creg[i2], k);
                    creg[i2] -= cik * creg[k];
                }
            }
            if (lane >= 16) {
                #pragma unroll
                for (int i2 = 0; i2 < 16; i2++) sInv[i2 * 20 + col] = creg[i2];
            }
        }
        __syncthreads();                           // Inv ready

        // D: Kt = -Inv @ Qux (4x4 reg tiles, float4)  ||  kt = -Inv @ qu (+ cost)
        if (tid < 32) {
            const int a0 = (tid >> 3) * 4, i0 = (tid & 7) * 4;
            float4 r0 = {0,0,0,0}, r1 = {0,0,0,0}, r2 = {0,0,0,0}, r3 = {0,0,0,0};
            #pragma unroll
            for (int c0 = 0; c0 < 16; c0 += 4) {
                const float4 v0 = *(const float4*)(sInv + (a0+0)*20 + c0);
                const float4 v1 = *(const float4*)(sInv + (a0+1)*20 + c0);
                const float4 v2 = *(const float4*)(sInv + (a0+2)*20 + c0);
                const float4 v3 = *(const float4*)(sInv + (a0+3)*20 + c0);
                const float4 q0 = *(const float4*)(sQt + (32+c0+0)*48 + i0);
                const float4 q1 = *(const float4*)(sQt + (32+c0+1)*48 + i0);
                const float4 q2 = *(const float4*)(sQt + (32+c0+2)*48 + i0);
                const float4 q3 = *(const float4*)(sQt + (32+c0+3)*48 + i0);
                r0.x += v0.x*q0.x + v0.y*q1.x + v0.z*q2.x + v0.w*q3.x;
                r0.y += v0.x*q0.y + v0.y*q1.y + v0.z*q2.y + v0.w*q3.y;
                r0.z += v0.x*q0.z + v0.y*q1.z + v0.z*q2.z + v0.w*q3.z;
                r0.w += v0.x*q0.w + v0.y*q1.w + v0.z*q2.w + v0.w*q3.w;
                r1.x += v1.x*q0.x + v1.y*q1.x + v1.z*q2.x + v1.w*q3.x;
                r1.y += v1.x*q0.y + v1.y*q1.y + v1.z*q2.y + v1.w*q3.y;
                r1.z += v1.x*q0.z + v1.y*q1.z + v1.z*q2.z + v1.w*q3.z;
                r1.w += v1.x*q0.w + v1.y*q1.w + v1.z*q2.w + v1.w*q3.w;
                r2.x += v2.x*q0.x + v2.y*q1.x + v2.z*q2.x + v2.w*q3.x;
                r2.y += v2.x*q0.y + v2.y*q1.y + v2.z*q2.y + v2.w*q3.y;
                r2.z += v2.x*q0.z + v2.y*q1.z + v2.z*q2.z + v2.w*q3.z;
                r2.w += v2.x*q0.w + v2.y*q1.w + v2.z*q2.w + v2.w*q3.w;
                r3.x += v3.x*q0.x + v3.y*q1.x + v3.z*q2.x + v3.w*q3.x;
                r3.y += v3.x*q0.y + v3.y*q1.y + v3.z*q2.y + v3.w*q3.y;
                r3.z += v3.x*q0.z + v3.y*q1.z + v3.z*q2.z + v3.w*q3.z;
                r3.w += v3.x*q0.w + v3.y*q1.w + v3.z*q2.w + v3.w*q3.w;
            }
            *(float4*)(sKt + (a0+0)*32 + i0) = make_float4(-r0.x,-r0.y,-r0.z,-r0.w);
            *(float4*)(sKt + (a0+1)*32 + i0) = make_float4(-r1.x,-r1.y,-r1.z,-r1.w);
            *(float4*)(sKt + (a0+2)*32 + i0) = make_float4(-r2.x,-r2.y,-r2.z,-r2.w);
            *(float4*)(sKt + (a0+3)*32 + i0) = make_float4(-r3.x,-r3.y,-r3.z,-r3.w);
        } else if (tid < 48) {
            const int a = tid - 32;
            float acc = 0.f;
            #pragma unroll
            for (int cc = 0; cc < 16; cc++) {
                int c = (a + cc) & 15;
                acc += sInv[a*20 + c] * sqt[32 + c];
            }
            skt[a] = -acc;
            scc[32 + a] += -0.5f * sqt[32 + a] * acc;   // 0.5 * qu_a * kt_a
        }
        __syncthreads();                           // Kt, kt ready

        // E: Vn = Qxx + Qxu Kt (4x4 reg tiles) ; vn ; store gains
        if (tid < 64) {
            const int g = tid >> 3;
            const int i0 = g * 4, j0 = (tid & 7) * 4;
            float4 v0 = *(const float4*)(sQt + (i0+0)*48 + j0);
            float4 v1 = *(const float4*)(sQt + (i0+1)*48 + j0);
            float4 v2 = *(const float4*)(sQt + (i0+2)*48 + j0);
            float4 v3 = *(const float4*)(sQt + (i0+3)*48 + j0);
            #pragma unroll
            for (int ch = 0; ch < 4; ch++) {
                const int c0 = ((ch + g) & 3) * 4;   // rotate: breaks bank conflicts
                const float4 a0v = *(const float4*)(sQt + (i0+0)*48 + 32 + c0);
                const float4 a1v = *(const float4*)(sQt + (i0+1)*48 + 32 + c0);
                const float4 a2v = *(const float4*)(sQt + (i0+2)*48 + 32 + c0);
                const float4 a3v = *(const float4*)(sQt + (i0+3)*48 + 32 + c0);
                const float4 k0 = *(const float4*)(sKt + (c0+0)*32 + j0);
                const float4 k1 = *(const float4*)(sKt + (c0+1)*32 + j0);
                const float4 k2 = *(const float4*)(sKt + (c0+2)*32 + j0);
                const float4 k3 = *(const float4*)(sKt + (c0+3)*32 + j0);
                v0.x += a0v.x*k0.x + a0v.y*k1.x + a0v.z*k2.x + a0v.w*k3.x;
                v0.y += a0v.x*k0.y + a0v.y*k1.y + a0v.z*k2.y + a0v.w*k3.y;
                v0.z += a0v.x*k0.z + a0v.y*k1.z + a0v.z*k2.z + a0v.w*k3.z;
                v0.w += a0v.x*k0.w + a0v.y*k1.w + a0v.z*k2.w + a0v.w*k3.w;
                v1.x += a1v.x*k0.x + a1v.y*k1.x + a1v.z*k2.x + a1v.w*k3.x;
                v1.y += a1v.x*k0.y + a1v.y*k1.y + a1v.z*k2.y + a1v.w*k3.y;
                v1.z += a1v.x*k0.z + a1v.y*k1.z + a1v.z*k2.z + a1v.w*k3.z;
                v1.w += a1v.x*k0.w + a1v.y*k1.w + a1v.z*k2.w + a1v.w*k3.w;
                v2.x += a2v.x*k0.x + a2v.y*k1.x + a2v.z*k2.x + a2v.w*k3.x;
                v2.y += a2v.x*k0.y + a2v.y*k1.y + a2v.z*k2.y + a2v.w*k3.y;
                v2.z += a2v.x*k0.z + a2v.y*k1.z + a2v.z*k2.z + a2v.w*k3.z;
                v2.w += a2v.x*k0.w + a2v.y*k1.w + a2v.z*k2.w + a2v.w*k3.w;
                v3.x += a3v.x*k0.x + a3v.y*k1.x + a3v.z*k2.x + a3v.w*k3.x;
                v3.y += a3v.x*k0.y + a3v.y*k1.y + a3v.z*k2.y + a3v.w*k3.y;
                v3.z += a3v.x*k0.z + a3v.y*k1.z + a3v.z*k2.z + a3v.w*k3.z;
                v3.w += a3v.x*k0.w + a3v.y*k1.w + a3v.z*k2.w + a3v.w*k3.w;
            }
            *(float4*)(sV + (i0+0)*36 + j0) = v0;
            *(float4*)(sV + (i0+1)*36 + j0) = v1;
            *(float4*)(sV + (i0+2)*36 + j0) = v2;
            *(float4*)(sV + (i0+3)*36 + j0) = v3;
        } else if (tid < 96) {
            const int i = tid - 64;
            float acc = sqt[i];
            #pragma unroll
            for (int aa = 0; aa < 16; aa++) {
                int a = (i + aa) & 15;
                acc += sQt[i*48 + 32 + a] * skt[a];
            }
            sv[i] = acc;
        } else if (tid < 228) {
            const int e = tid - 96;
            float* gdst = g_G + ((size_t)b * XT + t) * 528;
            float4 val;
            if (e < 128) val = *(const float4*)(sKt + e * 4);
            else         val = *(const float4*)(skt + (e - 128) * 4);
            *(float4*)(gdst + e * 4) = val;
        }
        __syncthreads();                           // V, v ready for next step
    }

    // ---- cost write (idle warp) runs concurrently with forward rollout ----
    if (tid == 128) {
        float c = 0.f;
        #pragma unroll
        for (int i = 0; i < 48; i++) c += scc[i];
        out[(size_t)XNB * XT * XNS + (size_t)XNB * XT * XNC + b] = c;
    }

    // =============== forward rollout: warp 0 only, shuffle-resident state ======
    if (tid < 32) {
        const int lane = tid;
        float* kb0 = sM;
        float* kb1 = sM + 544;
        float* out_x = out;
        float* out_u = out + (size_t)XNB * XT * XNS;
        float x = Xi[b * 32 + lane];
        {
            const float* src = g_G + (size_t)b * XT * 528;
            #pragma unroll
            for (int kk = 0; kk < 5; kk++) {
                int e = lane + kk * 32;
                if (e < 132) cpa16(kb0 + e * 4, src + e * 4);
            }
            cpa_commit();
        }
        int pb = 0;
        for (int t = 0; t < XT; t++) {
            cpa_wait0();
            __syncwarp();
            const float* kc = pb ? kb1 : kb0;
            const float d = x - scx[t * 32 + lane];
            float acc = 0.f;
            #pragma unroll
            for (int jj = 0; jj < 32; jj++) {
                int j = (lane + jj) & 31;
                float dj = __shfl_sync(0xffffffffu, d, j);
                if (lane < 16) acc += kc[lane * 32 + j] * dj;
            }
            float u = 0.f;
            if (lane < 16) {
                u = acc + kc[512 + lane];
                out_u[((size_t)b * XT + t) * XNC + lane] = u;
            }
            out_x[((size_t)b * XT + t) * XNS + lane] = x;
            if (t + 1 < XT) {
                const float* src = g_G + ((size_t)b * XT + t + 1) * 528;
                float* kn = pb ? kb0 : kb1;
                #pragma unroll
                for (int kk = 0; kk < 5; kk++) {
                    int e = lane + kk * 32;
                    if (e < 132) cpa16(kn + e * 4, src + e * 4);
                }
                cpa_commit();
            }
            float xn = 0.f, xn2 = 0.f;
            #pragma unroll
            for (int jj = 0; jj < 32; jj++) {
                int j = (lane + jj) & 31;
                float xj = __shfl_sync(0xffffffffu, x, j);
                if (jj & 1) xn2 += sF[lane * 48 + j] * xj;
                else        xn  += sF[lane * 48 + j] * xj;
            }
            #pragma unroll
            for (int aa = 0; aa < 16; aa++) {
                int a2 = (lane + aa) & 15;
                float ua = __shfl_sync(0xffffffffu, u, a2);
                if (aa & 1) xn2 += sF[lane * 48 + 32 + a2] * ua;
                else        xn  += sF[lane * 48 + 32 + a2] * ua;
            }
            x = xn + xn2;
            pb ^= 1;
        }
    }
}

extern "C" void kernel_launch(void* const* d_in, const int* in_sizes, int n_in,
                              void* d_out, int out_size) {
    const float* x_init = (const float*)d_in[0];
    const float* Q      = (const float*)d_in[1];
    const float* p      = (const float*)d_in[2];
    const float* A      = (const float*)d_in[3];
    const float* B      = (const float*)d_in[4];
    float* out = (float*)d_out;
    lqr_kernel<<<XNB, 256>>>(x_init, Q, p, A, B, out);
}

// round 11
// speedup vs baseline: 1.2634x; 1.0241x over previous
#include <cuda_runtime.h>

#define XNS 32
#define XNC 16
#define XT  64
#define XNB 512
#define XSC 48

// gain scratch: per (b,t) 528 floats = [K 16x32][k 16]
__device__ float g_G[(size_t)XNB * XT * 528];

__device__ __forceinline__ void cpa16(void* s, const void* g) {
    unsigned sa = (unsigned)__cvta_generic_to_shared(s);
    asm volatile("cp.async.cg.shared.global [%0], [%1], 16;" :: "r"(sa), "l"(g));
}
__device__ __forceinline__ void cpa_commit() { asm volatile("cp.async.commit_group;"); }
__device__ __forceinline__ void cpa_wait0()  { asm volatile("cp.async.wait_group 0;"); }

__global__ __launch_bounds__(256, 4)
void lqr_kernel(const float* __restrict__ Xi, const float* __restrict__ Qg,
                const float* __restrict__ Pg, const float* __restrict__ Ag,
                const float* __restrict__ Bg, float* __restrict__ out)
{
    __shared__ __align__(16) float sF[32 * 48];
    __shared__ __align__(16) float sV[32 * 36];     // padded rows
    __shared__ __align__(16) float sM[32 * 48];     // backward: V@F ; forward: K dbl-buf
    __shared__ __align__(16) float sQt[48 * 48];
    __shared__ __align__(16) float sQraw[48 * 48];
    __shared__ __align__(16) float scx[64 * 32];
    __shared__ __align__(16) float sKt[16 * 32];
    __shared__ __align__(16) float skt[16];
    __shared__ __align__(16) float sqt[48];
    __shared__ float sv[32];
    __shared__ __align__(16) float sInv[16 * 20];   // stride 20: float4-loadable rows
    __shared__ __align__(16) float sp[48];
    __shared__ float scc[48];                       // cost accumulators

    const int b   = blockIdx.x;
    const int tid = threadIdx.x;
    const float* Qb = Qg + (size_t)b * XT * XSC * XSC;
    const float* Pb = Pg + (size_t)b * XT * XSC;

    // ---- B-phase tile map: 78 lower-triangle tiles + 6 upper tiles of uu block
    int i0B = 0, j0B = 0;
    if (tid < 78) {
        int e = tid, r = 0;
        while (e >= r + 1) { e -= r + 1; r++; }
        i0B = r * 4; j0B = e * 4;
    } else if (tid < 84) {
        const int q = tid - 78;                    // (8,9)(8,10)(8,11)(9,10)(9,11)(10,11)
        const int rt = (q < 3) ? 8 : ((q < 5) ? 9 : 10);
        const int ct = (q < 3) ? (9 + q) : ((q < 5) ? (7 + q) : 11);
        i0B = rt * 4; j0B = ct * 4;
    }
    // ---- mirror map: 60 strict-upper tiles excluding uu block (threads 64..123)
    int mSrc = 0, mDst = 0;
    if (tid >= 64 && tid < 124) {
        const int myT = tid - 64;
        int cnt = 0;
        for (int rt = 0; rt < 12; rt++)
            for (int ct = rt + 1; ct < 12; ct++) {
                if (rt >= 8 && ct >= 8) continue;
                if (cnt == myT) { mSrc = (ct * 4) * 48 + rt * 4;
                                  mDst = (rt * 4) * 48 + ct * 4; }
                cnt++;
            }
    }

    // ---- setup ----
    for (int e = tid; e < 32 * 48; e += 256) {
        int s = e / 48, j = e % 48;
        sF[e] = (j < 32) ? Ag[s * 32 + j] : Bg[s * 16 + (j - 32)];
    }
    for (int e = tid; e < 32 * 36; e += 256) sV[e] = 0.f;
    if (tid < 32) sv[tid] = 0.f;
    if (tid < 48) scc[tid] = 0.f;
    {   // prefetch Q(T-1), p(T-1)
        const float* qsrc = Qb + (size_t)(XT - 1) * XSC * XSC;
        #pragma unroll
        for (int kk = 0; kk < 3; kk++) { int idx = tid + kk * 256;
            if (idx < 576) cpa16(sQraw + idx * 4, qsrc + idx * 4); }
        if (tid < 12) cpa16(sp + tid * 4, Pb + (size_t)(XT - 1) * XSC + tid * 4);
        cpa_commit();
    }
    __syncthreads();

    // nominal trajectory cx[t] (warp 0)
    if (tid < 32) {
        scx[tid] = Xi[b * 32 + tid];
        for (int t = 1; t < XT; t++) {
            __syncwarp();
            float acc = 0.f;
            #pragma unroll
            for (int jj = 0; jj < 32; jj++) {
                int j = (tid + jj) & 31;
                acc += sF[tid * 48 + j] * scx[(t - 1) * 32 + j];
            }
            scx[t * 32 + tid] = acc;
        }
    }
    __syncthreads();

    // =============== backward Riccati ===============
    for (int t = XT - 1; t >= 0; t--) {
        // A: M = V @ F (V symmetric: row reads)
        if (tid < 192) {
            const int s0 = (tid / 24) * 4, j0 = (tid % 24) * 2;
            float a00=0,a01=0,a10=0,a11=0,a20=0,a21=0,a30=0,a31=0;
            #pragma unroll 8
            for (int r = 0; r < 32; r++) {
                const float4 vv = *(const float4*)(sV + r * 36 + s0);
                const float2 ff = *(const float2*)(sF + r * 48 + j0);
                a00 += vv.x*ff.x; a01 += vv.x*ff.y; a10 += vv.y*ff.x; a11 += vv.y*ff.y;
                a20 += vv.z*ff.x; a21 += vv.z*ff.y; a30 += vv.w*ff.x; a31 += vv.w*ff.y;
            }
            *(float2*)(sM + (s0+0)*48 + j0) = make_float2(a00,a01);
            *(float2*)(sM + (s0+1)*48 + j0) = make_float2(a10,a11);
            *(float2*)(sM + (s0+2)*48 + j0) = make_float2(a20,a21);
            *(float2*)(sM + (s0+3)*48 + j0) = make_float2(a30,a31);
        }
        cpa_wait0();
        __syncthreads();                           // Qraw(t), p(t), M ready

        // B: Qt = Qraw + F^T M -- 84 tiles (lower triangle + full uu block)  ||  qt
        if (tid < 84) {
            const int i0 = i0B, j0 = j0B;
            float4 c0 = *(const float4*)(sQraw + (i0+0)*48 + j0);
            float4 c1 = *(const float4*)(sQraw + (i0+1)*48 + j0);
            float4 c2 = *(const float4*)(sQraw + (i0+2)*48 + j0);
            float4 c3 = *(const float4*)(sQraw + (i0+3)*48 + j0);
            #pragma unroll 4
            for (int s = 0; s < 32; s++) {
                const float4 fa = *(const float4*)(sF + s * 48 + i0);
                const float4 mb = *(const float4*)(sM + s * 48 + j0);
                c0.x += fa.x*mb.x; c0.y += fa.x*mb.y; c0.z += fa.x*mb.z; c0.w += fa.x*mb.w;
                c1.x += fa.y*mb.x; c1.y += fa.y*mb.y; c1.z += fa.y*mb.z; c1.w += fa.y*mb.w;
                c2.x += fa.z*mb.x; c2.y += fa.z*mb.y; c2.z += fa.z*mb.z; c2.w += fa.z*mb.w;
                c3.x += fa.w*mb.x; c3.y += fa.w*mb.y; c3.z += fa.w*mb.z; c3.w += fa.w*mb.w;
            }
            *(float4*)(sQt + (i0+0)*48 + j0) = c0;
            *(float4*)(sQt + (i0+1)*48 + j0) = c1;
            *(float4*)(sQt + (i0+2)*48 + j0) = c2;
            *(float4*)(sQt + (i0+3)*48 + j0) = c3;
        } else if (tid >= 208) {
            const int i = tid - 208;
            float tmp = 0.f;                       // (Qraw_x* · cx)_i
            #pragma unroll
            for (int jj = 0; jj < 32; jj++) {
                int j = (i + jj) & 31;
                tmp += sQraw[i * 48 + j] * scx[t * 32 + j];
            }
            float acc = sp[i] + tmp;
            #pragma unroll
            for (int s = 0; s < 32; s++) acc += sv[s] * sF[s * 48 + i];
            sqt[i] = acc;
            if (i < 32)                            // stage const: cx_i (0.5 tmp + p_i)
                scc[i] += scx[t * 32 + i] * (0.5f * tmp + sp[i]);
        }
        __syncthreads();                           // Qt(lower+uu), qt ready; Qraw free

        // C: prefetch next Q,p  +  warp-0 GJ inverse of Quu  +  mirror upper tiles
        if (t > 0) {
            const float* qsrc = Qb + (size_t)(t - 1) * XSC * XSC;
            #pragma unroll
            for (int kk = 0; kk < 3; kk++) { int idx = tid + kk * 256;
                if (idx < 576) cpa16(sQraw + idx * 4, qsrc + idx * 4); }
            if (tid < 12) cpa16(sp + tid * 4, Pb + (size_t)(t - 1) * XSC + tid * 4);
            cpa_commit();
        }
        if (tid < 32) {
            const int lane = tid, col = lane & 15;
            float creg[16];
            if (lane < 16) {
                #pragma unroll
                for (int i2 = 0; i2 < 16; i2++) creg[i2] = sQt[(32+i2)*48 + 32 + lane];
            } else {
                #pragma unroll
                for (int i2 = 0; i2 < 16; i2++) creg[i2] = (i2 == col) ? 1.f : 0.f;
            }
            #pragma unroll
            for (int k = 0; k < 16; k++) {
                const float ck  = __shfl_sync(0xffffffffu, creg[k], k);
                const float piv = 1.0f / ck;
                creg[k] *= piv;
                #pragma unroll
                for (int i2 = 0; i2 < 16; i2++) {
                    if (i2 == k) continue;
                    const float cik = __shfl_sync(0xffffffffu, creg[i2], k);
                    creg[i2] -= cik * creg[k];
                }
            }
            if (lane >= 16) {
                #pragma unroll
                for (int i2 = 0; i2 < 16; i2++) sInv[i2 * 20 + col] = creg[i2];
            }
        } else if (tid >= 64 && tid < 124) {
            // mirror: upper tile <- transpose(lower tile). 4 LDS.128 + 4 STS.128.
            const float4 v0 = *(const float4*)(sQt + mSrc + 0*48);
            const float4 v1 = *(const float4*)(sQt + mSrc + 1*48);
            const float4 v2 = *(const float4*)(sQt + mSrc + 2*48);
            const float4 v3 = *(const float4*)(sQt + mSrc + 3*48);
            *(float4*)(sQt + mDst + 0*48) = make_float4(v0.x, v1.x, v2.x, v3.x);
            *(float4*)(sQt + mDst + 1*48) = make_float4(v0.y, v1.y, v2.y, v3.y);
            *(float4*)(sQt + mDst + 2*48) = make_float4(v0.z, v1.z, v2.z, v3.z);
            *(float4*)(sQt + mDst + 3*48) = make_float4(v0.w, v1.w, v2.w, v3.w);
        }
        __syncthreads();                           // Inv + full symmetric Qt ready

        // D: Kt = -Inv @ Qux (4x4 reg tiles, float4)  ||  kt = -Inv @ qu (+ cost)
        if (tid < 32) {
            const int a0 = (tid >> 3) * 4, i0 = (tid & 7) * 4;
            float4 r0 = {0,0,0,0}, r1 = {0,0,0,0}, r2 = {0,0,0,0}, r3 = {0,0,0,0};
            #pragma unroll
            for (int c0 = 0; c0 < 16; c0 += 4) {
                const float4 v0 = *(const float4*)(sInv + (a0+0)*20 + c0);
                const float4 v1 = *(const float4*)(sInv + (a0+1)*20 + c0);
                const float4 v2 = *(const float4*)(sInv + (a0+2)*20 + c0);
                const float4 v3 = *(const float4*)(sInv + (a0+3)*20 + c0);
                const float4 q0 = *(const float4*)(sQt + (32+c0+0)*48 + i0);
                const float4 q1 = *(const float4*)(sQt + (32+c0+1)*48 + i0);
                const float4 q2 = *(const float4*)(sQt + (32+c0+2)*48 + i0);
                const float4 q3 = *(const float4*)(sQt + (32+c0+3)*48 + i0);
                r0.x += v0.x*q0.x + v0.y*q1.x + v0.z*q2.x + v0.w*q3.x;
                r0.y += v0.x*q0.y + v0.y*q1.y + v0.z*q2.y + v0.w*q3.y;
                r0.z += v0.x*q0.z + v0.y*q1.z + v0.z*q2.z + v0.w*q3.z;
                r0.w += v0.x*q0.w + v0.y*q1.w + v0.z*q2.w + v0.w*q3.w;
                r1.x += v1.x*q0.x + v1.y*q1.x + v1.z*q2.x + v1.w*q3.x;
                r1.y += v1.x*q0.y + v1.y*q1.y + v1.z*q2.y + v1.w*q3.y;
                r1.z += v1.x*q0.z + v1.y*q1.z + v1.z*q2.z + v1.w*q3.z;
                r1.w += v1.x*q0.w + v1.y*q1.w + v1.z*q2.w + v1.w*q3.w;
                r2.x += v2.x*q0.x + v2.y*q1.x + v2.z*q2.x + v2.w*q3.x;
                r2.y += v2.x*q0.y + v2.y*q1.y + v2.z*q2.y + v2.w*q3.y;
                r2.z += v2.x*q0.z + v2.y*q1.z + v2.z*q2.z + v2.w*q3.z;
                r2.w += v2.x*q0.w + v2.y*q1.w + v2.z*q2.w + v2.w*q3.w;
                r3.x += v3.x*q0.x + v3.y*q1.x + v3.z*q2.x + v3.w*q3.x;
                r3.y += v3.x*q0.y + v3.y*q1.y + v3.z*q2.y + v3.w*q3.y;
                r3.z += v3.x*q0.z + v3.y*q1.z + v3.z*q2.z + v3.w*q3.z;
                r3.w += v3.x*q0.w + v3.y*q1.w + v3.z*q2.w + v3.w*q3.w;
            }
            *(float4*)(sKt + (a0+0)*32 + i0) = make_float4(-r0.x,-r0.y,-r0.z,-r0.w);
            *(float4*)(sKt + (a0+1)*32 + i0) = make_float4(-r1.x,-r1.y,-r1.z,-r1.w);
            *(float4*)(sKt + (a0+2)*32 + i0) = make_float4(-r2.x,-r2.y,-r2.z,-r2.w);
            *(float4*)(sKt + (a0+3)*32 + i0) = make_float4(-r3.x,-r3.y,-r3.z,-r3.w);
        } else if (tid < 48) {
            const int a = tid - 32;
            float acc = 0.f;
            #pragma unroll
            for (int cc = 0; cc < 16; cc++) {
                int c = (a + cc) & 15;
                acc += sInv[a*20 + c] * sqt[32 + c];
            }
            skt[a] = -acc;
            scc[32 + a] += -0.5f * sqt[32 + a] * acc;   // 0.5 * qu_a * kt_a
        }
        __syncthreads();                           // Kt, kt ready

        // E: Vn = Qxx + Qxu Kt (4x4 reg tiles) ; vn ; store gains
        if (tid < 64) {
            const int g = tid >> 3;
            const int i0 = g * 4, j0 = (tid & 7) * 4;
            float4 v0 = *(const float4*)(sQt + (i0+0)*48 + j0);
            float4 v1 = *(const float4*)(sQt + (i0+1)*48 + j0);
            float4 v2 = *(const float4*)(sQt + (i0+2)*48 + j0);
            float4 v3 = *(const float4*)(sQt + (i0+3)*48 + j0);
            #pragma unroll
            for (int ch = 0; ch < 4; ch++) {
                const int c0 = ((ch + g) & 3) * 4;   // rotate: breaks bank conflicts
                const float4 a0v = *(const float4*)(sQt + (i0+0)*48 + 32 + c0);
                const float4 a1v = *(const float4*)(sQt + (i0+1)*48 + 32 + c0);
                const float4 a2v = *(const float4*)(sQt + (i0+2)*48 + 32 + c0);
                const float4 a3v = *(const float4*)(sQt + (i0+3)*48 + 32 + c0);
                const float4 k0 = *(const float4*)(sKt + (c0+0)*32 + j0);
                const float4 k1 = *(const float4*)(sKt + (c0+1)*32 + j0);
                const float4 k2 = *(const float4*)(sKt + (c0+2)*32 + j0);
                const float4 k3 = *(const float4*)(sKt + (c0+3)*32 + j0);
                v0.x += a0v.x*k0.x + a0v.y*k1.x + a0v.z*k2.x + a0v.w*k3.x;
                v0.y += a0v.x*k0.y + a0v.y*k1.y + a0v.z*k2.y + a0v.w*k3.y;
                v0.z += a0v.x*k0.z + a0v.y*k1.z + a0v.z*k2.z + a0v.w*k3.z;
                v0.w += a0v.x*k0.w + a0v.y*k1.w + a0v.z*k2.w + a0v.w*k3.w;
                v1.x += a1v.x*k0.x + a1v.y*k1.x + a1v.z*k2.x + a1v.w*k3.x;
                v1.y += a1v.x*k0.y + a1v.y*k1.y + a1v.z*k2.y + a1v.w*k3.y;
                v1.z += a1v.x*k0.z + a1v.y*k1.z + a1v.z*k2.z + a1v.w*k3.z;
                v1.w += a1v.x*k0.w + a1v.y*k1.w + a1v.z*k2.w + a1v.w*k3.w;
                v2.x += a2v.x*k0.x + a2v.y*k1.x + a2v.z*k2.x + a2v.w*k3.x;
                v2.y += a2v.x*k0.y + a2v.y*k1.y + a2v.z*k2.y + a2v.w*k3.y;
                v2.z += a2v.x*k0.z + a2v.y*k1.z + a2v.z*k2.z + a2v.w*k3.z;
                v2.w += a2v.x*k0.w + a2v.y*k1.w + a2v.z*k2.w + a2v.w*k3.w;
                v3.x += a3v.x*k0.x + a3v.y*k1.x + a3v.z*k2.x + a3v.w*k3.x;
                v3.y += a3v.x*k0.y + a3v.y*k1.y + a3v.z*k2.y + a3v.w*k3.y;
                v3.z += a3v.x*k0.z + a3v.y*k1.z + a3v.z*k2.z + a3v.w*k3.z;
                v3.w += a3v.x*k0.w + a3v.y*k1.w + a3v.z*k2.w + a3v.w*k3.w;
            }
            *(float4*)(sV + (i0+0)*36 + j0) = v0;
            *(float4*)(sV + (i0+1)*36 + j0) = v1;
            *(float4*)(sV + (i0+2)*36 + j0) = v2;
            *(float4*)(sV + (i0+3)*36 + j0) = v3;
        } else if (tid < 96) {
            const int i = tid - 64;
            float acc = sqt[i];
            #pragma unroll
            for (int aa = 0; aa < 16; aa++) {
                int a = (i + aa) & 15;
                acc += sQt[i*48 + 32 + a] * skt[a];
            }
            sv[i] = acc;
        } else if (tid < 228) {
            const int e = tid - 96;
            float* gdst = g_G + ((size_t)b * XT + t) * 528;
            float4 val;
            if (e < 128) val = *(const float4*)(sKt + e * 4);
            else         val = *(const float4*)(skt + (e - 128) * 4);
            *(float4*)(gdst + e * 4) = val;
        }
        __syncthreads();                           // V, v ready for next step
    }

    // ---- cost write (idle warp) runs concurrently with forward rollout ----
    if (tid == 128) {
        float c = 0.f;
        #pragma unroll
        for (int i = 0; i < 48; i++) c += scc[i];
        out[(size_t)XNB * XT * XNS + (size_t)XNB * XT * XNC + b] = c;
    }

    // =============== forward rollout: warp 0 only, shuffle-resident state ======
    if (tid < 32) {
        const int lane = tid;
        float* kb0 = sM;
        float* kb1 = sM + 544;
        float* out_x = out;
        float* out_u = out + (size_t)XNB * XT * XNS;
        float x = Xi[b * 32 + lane];
        {
            const float* src = g_G + (size_t)b * XT * 528;
            #pragma unroll
            for (int kk = 0; kk < 5; kk++) {
                int e = lane + kk * 32;
                if (e < 132) cpa16(kb0 + e * 4, src + e * 4);
            }
            cpa_commit();
        }
        int pb = 0;
        for (int t = 0; t < XT; t++) {
            cpa_wait0();
            __syncwarp();
            const float* kc = pb ? kb1 : kb0;
            const float d = x - scx[t * 32 + lane];
            float acc = 0.f;
            #pragma unroll
            for (int jj = 0; jj < 32; jj++) {
                int j = (lane + jj) & 31;
                float dj = __shfl_sync(0xffffffffu, d, j);
                if (lane < 16) acc += kc[lane * 32 + j] * dj;
            }
            float u = 0.f;
            if (lane < 16) {
                u = acc + kc[512 + lane];
                out_u[((size_t)b * XT + t) * XNC + lane] = u;
            }
            out_x[((size_t)b * XT + t) * XNS + lane] = x;
            if (t + 1 < XT) {
                const float* src = g_G + ((size_t)b * XT + t + 1) * 528;
                float* kn = pb ? kb0 : kb1;
                #pragma unroll
                for (int kk = 0; kk < 5; kk++) {
                    int e = lane + kk * 32;
                    if (e < 132) cpa16(kn + e * 4, src + e * 4);
                }
                cpa_commit();
            }
            float xn = 0.f, xn2 = 0.f;
            #pragma unroll
            for (int jj = 0; jj < 32; jj++) {
                int j = (lane + jj) & 31;
                float xj = __shfl_sync(0xffffffffu, x, j);
                if (jj & 1) xn2 += sF[lane * 48 + j] * xj;
                else        xn  += sF[lane * 48 + j] * xj;
            }
            #pragma unroll
            for (int aa = 0; aa < 16; aa++) {
                int a2 = (lane + aa) & 15;
                float ua = __shfl_sync(0xffffffffu, u, a2);
                if (aa & 1) xn2 += sF[lane * 48 + 32 + a2] * ua;
                else        xn  += sF[lane * 48 + 32 + a2] * ua;
            }
            x = xn + xn2;
            pb ^= 1;
        }
    }
}

extern "C" void kernel_launch(void* const* d_in, const int* in_sizes, int n_in,
                              void* d_out, int out_size) {
    const float* x_init = (const float*)d_in[0];
    const float* Q      = (const float*)d_in[1];
    const float* p      = (const float*)d_in[2];
    const float* A      = (const float*)d_in[3];
    const float* B      = (const float*)d_in[4];
    float* out = (float*)d_out;
    lqr_kernel<<<XNB, 256>>>(x_init, Q, p, A, B, out);
}